// round 6
// baseline (speedup 1.0000x reference)
#include <cuda_runtime.h>
#include <math.h>
#include <stdint.h>

// Problem constants
#define BB 4
#define HH 16
#define SS 2048
#define DD 1024
#define HD 64
#define MROWS (BB * SS)   // 8192

// ---------------------------------------------------------------------------
// Scratch (no allocations allowed -> __device__ globals)
// ---------------------------------------------------------------------------
__device__ float g_Q[BB * HH * SS * HD];
__device__ float g_K[BB * HH * SS * HD];
__device__ float g_V[BB * HH * SS * HD];
__device__ float g_ctx[BB * SS * DD];
__device__ float g_Xr[MROWS * DD];        // tf32-rounded x
__device__ float g_Wr[4 * DD * DD];       // tf32-rounded Wq,Wk,Wv,Wo

// ---------------------------------------------------------------------------
// helpers
// ---------------------------------------------------------------------------
__device__ __forceinline__ uint32_t smem_u32(const void* p) {
    uint32_t a;
    asm("{ .reg .u64 t; cvta.to.shared.u64 t, %1; cvt.u32.u64 %0, t; }"
        : "=r"(a) : "l"(p));
    return a;
}

__device__ __forceinline__ uint32_t f2tf32(float f) {
    uint32_t u;
    asm("cvt.rna.tf32.f32 %0, %1;" : "=r"(u) : "f"(f));
    return u;
}

__device__ __forceinline__ float roundtf(float f) {
    return __uint_as_float(f2tf32(f));
}

// mma.sync m16n8k8 tf32, fp32 accumulate (in place on d)
__device__ __forceinline__ void mma_tf32(float d[4], const uint32_t a[4],
                                         const uint32_t b[2]) {
    asm volatile(
        "mma.sync.aligned.m16n8k8.row.col.f32.tf32.tf32.f32 "
        "{%0,%1,%2,%3}, {%4,%5,%6,%7}, {%8,%9}, {%0,%1,%2,%3};"
        : "+f"(d[0]), "+f"(d[1]), "+f"(d[2]), "+f"(d[3])
        : "r"(a[0]), "r"(a[1]), "r"(a[2]), "r"(a[3]), "r"(b[0]), "r"(b[1]));
}

#define LDSM4(R0, R1, R2, R3, addr) \
    asm volatile("ldmatrix.sync.aligned.m8n8.x4.shared.b16 {%0,%1,%2,%3}, [%4];" \
                 : "=r"(R0), "=r"(R1), "=r"(R2), "=r"(R3) : "r"(addr))

// ---------------------------------------------------------------------------
// Elementwise tf32 pre-round (float4 vectorized)
// ---------------------------------------------------------------------------
__global__ void round_kernel(const float* __restrict__ in,
                             float* __restrict__ out, int n4)
{
    int i = blockIdx.x * blockDim.x + threadIdx.x;
    if (i < n4) {
        float4 v = ((const float4*)in)[i];
        v.x = roundtf(v.x);
        v.y = roundtf(v.y);
        v.z = roundtf(v.z);
        v.w = roundtf(v.w);
        ((float4*)out)[i] = v;
    }
}

// ===========================================================================
// tf32 mma.sync GEMM with ldmatrix fragments (inputs pre-rounded to tf32).
// Y[m][n] = sum_k X[m][k]*W[n][k] + bias[n].
// CTA tile 128x128, BK=32, 8 warps (4m x 2n), warp tile 32x64.
// ===========================================================================
#define GBK 32
#define GPAD 36
#define GSTAGE_FLOATS (128 * GPAD)
#define GSTAGE_BYTES  (2 * GSTAGE_FLOATS * 4)
#define GNSTAGE 3
#define GEMM_SMEM (GNSTAGE * GSTAGE_BYTES)

__device__ __forceinline__ void gemm_issue_loads(
    const float* __restrict__ X, const float* __restrict__ W,
    int m0, int n0, int tid, uint32_t stage_addr, int k0)
{
#pragma unroll
    for (int t = 0; t < 4; ++t) {
        int idx = tid + t * 256;
        int row = idx >> 3;
        int c = idx & 7;
        const float* src = X + (size_t)(m0 + row) * 1024 + k0 + c * 4;
        uint32_t dst = stage_addr + row * 144 + c * 16;
        asm volatile("cp.async.cg.shared.global [%0], [%1], 16;"
                     :: "r"(dst), "l"(src));
    }
#pragma unroll
    for (int t = 0; t < 4; ++t) {
        int idx = tid + t * 256;
        int row = idx >> 3;
        int c = idx & 7;
        const float* src = W + (size_t)(n0 + row) * 1024 + k0 + c * 4;
        uint32_t dst = stage_addr + 18432 + row * 144 + c * 16;
        asm volatile("cp.async.cg.shared.global [%0], [%1], 16;"
                     :: "r"(dst), "l"(src));
    }
}

template <bool BHSD, bool ROUND>
__global__ __launch_bounds__(256)
void gemm_mma_kernel(const float* __restrict__ X, const float* __restrict__ W,
                     const float* __restrict__ bias, float* __restrict__ Y)
{
    extern __shared__ __align__(16) float smem[];
    const uint32_t sb = smem_u32(smem);
    const int tid = threadIdx.x;
    const int wid = tid >> 5;
    const int lane = tid & 31;
    const int wm = wid >> 1;
    const int wn = wid & 1;
    const int m0 = blockIdx.y * 128;
    const int n0 = blockIdx.x * 128;

    const int lr = lane >> 2;
    const int lc = lane & 3;

    // per-lane ldmatrix byte offsets (relative to stage base)
    const uint32_t a_off = ((wm * 32 + (lane & 15)) * GPAD + ((lane >> 4) << 2)) * 4;
    const uint32_t b_off = 18432 +
        ((wn * 64 + ((lane >> 4) << 3) + (lane & 7)) * GPAD + (((lane >> 3) & 1) << 2)) * 4;

    float acc[2][8][4];
#pragma unroll
    for (int mt = 0; mt < 2; ++mt)
#pragma unroll
        for (int nt = 0; nt < 8; ++nt)
#pragma unroll
            for (int i = 0; i < 4; ++i) acc[mt][nt][i] = 0.0f;

    gemm_issue_loads(X, W, m0, n0, tid, sb + 0 * GSTAGE_BYTES, 0);
    asm volatile("cp.async.commit_group;" ::: "memory");
    gemm_issue_loads(X, W, m0, n0, tid, sb + 1 * GSTAGE_BYTES, GBK);
    asm volatile("cp.async.commit_group;" ::: "memory");

    const int NK = 1024 / GBK;
    for (int s = 0; s < NK; ++s) {
        int t = s + 2;
        if (t < NK)
            gemm_issue_loads(X, W, m0, n0, tid,
                             sb + (t % GNSTAGE) * GSTAGE_BYTES, t * GBK);
        asm volatile("cp.async.commit_group;" ::: "memory");
        asm volatile("cp.async.wait_group 2;" ::: "memory");
        __syncthreads();

        const uint32_t st_b = sb + (s % GNSTAGE) * GSTAGE_BYTES;

#pragma unroll
        for (int kk = 0; kk < 4; ++kk) {
            uint32_t af[2][4];
            LDSM4(af[0][0], af[0][1], af[0][2], af[0][3],
                  st_b + a_off + kk * 32);
            LDSM4(af[1][0], af[1][1], af[1][2], af[1][3],
                  st_b + a_off + 16 * GPAD * 4 + kk * 32);
            uint32_t bf[8][2];
#pragma unroll
            for (int p = 0; p < 4; ++p) {
                LDSM4(bf[2 * p][0], bf[2 * p][1], bf[2 * p + 1][0], bf[2 * p + 1][1],
                      st_b + b_off + p * (16 * GPAD * 4) + kk * 32);
            }
#pragma unroll
            for (int mt = 0; mt < 2; ++mt)
#pragma unroll
                for (int nt = 0; nt < 8; ++nt)
                    mma_tf32(acc[mt][nt], af[mt], bf[nt]);
        }
        __syncthreads();
    }

#pragma unroll
    for (int nt = 0; nt < 8; ++nt) {
        int ncol = n0 + wn * 64 + nt * 8 + 2 * lc;
        float b0 = __ldg(&bias[ncol]);
        float b1 = __ldg(&bias[ncol + 1]);
#pragma unroll
        for (int mt = 0; mt < 2; ++mt) {
            int m = m0 + wm * 32 + mt * 16 + lr;
            float2 v0 = make_float2(acc[mt][nt][0] + b0, acc[mt][nt][1] + b1);
            float2 v1 = make_float2(acc[mt][nt][2] + b0, acc[mt][nt][3] + b1);
            if (ROUND) {
                v0.x = roundtf(v0.x); v0.y = roundtf(v0.y);
                v1.x = roundtf(v1.x); v1.y = roundtf(v1.y);
            }
            if (BHSD) {
                int b   = m >> 11;
                int sq  = m & 2047;
                int h   = ncol >> 6;
                int dd  = ncol & 63;
                float* d0 = &Y[(((size_t)(b * HH + h) * SS) + sq) * HD + dd];
                *(float2*)d0 = v0;
                int m8 = m + 8;
                int b8 = m8 >> 11;
                int sq8 = m8 & 2047;
                float* d1 = &Y[(((size_t)(b8 * HH + h) * SS) + sq8) * HD + dd];
                *(float2*)d1 = v1;
            } else {
                *(float2*)&Y[(size_t)m * DD + ncol] = v0;
                *(float2*)&Y[(size_t)(m + 8) * DD + ncol] = v1;
            }
        }
    }
}

// ---------------------------------------------------------------------------
// RoPE in-place on [B, H, S, 64]; outputs rounded to tf32.
// ---------------------------------------------------------------------------
__global__ void rope_kernel(float* __restrict__ P,
                            const float* __restrict__ cosb,
                            const float* __restrict__ sinb)
{
    int idx = blockIdx.x * blockDim.x + threadIdx.x;
    int i = idx & 31;
    int bhs = idx >> 5;
    int s = bhs & (SS - 1);
    float* p = P + (size_t)bhs * HD;
    float x0 = p[i];
    float x1 = p[i + 32];
    float c  = cosb[s * HD + i];
    float sn = sinb[s * HD + i];
    p[i]      = roundtf(x0 * c - x1 * sn);
    p[i + 32] = roundtf(x1 * c + x0 * sn);
}

// ===========================================================================
// Flash attention via mma.sync tf32 with ldmatrix fragments.
// BM=128 (8 warps x 16 rows), BN=64, HD=64. Q/K/V pre-rounded to tf32.
// ===========================================================================
#define FPAD 68
#define F_KS0 0
#define F_VS0 (2 * 64 * FPAD)
#define F_QP  (4 * 64 * FPAD)
#define FLASH_SMEM ((4 * 64 * FPAD + 128 * FPAD) * 4)   // 104448 bytes

__device__ __forceinline__ void flash_load_kv(
    const float* __restrict__ Kg, const float* __restrict__ Vg,
    int tid, uint32_t ks_addr, uint32_t vs_addr)
{
#pragma unroll
    for (int t = 0; t < 4; ++t) {
        int idx = tid + t * 256;
        int row = idx >> 4;
        int c4 = idx & 15;
        const float* srcK = Kg + row * HD + c4 * 4;
        const float* srcV = Vg + row * HD + c4 * 4;
        uint32_t dK = ks_addr + row * (FPAD * 4) + c4 * 16;
        uint32_t dV = vs_addr + row * (FPAD * 4) + c4 * 16;
        asm volatile("cp.async.cg.shared.global [%0], [%1], 16;" :: "r"(dK), "l"(srcK));
        asm volatile("cp.async.cg.shared.global [%0], [%1], 16;" :: "r"(dV), "l"(srcV));
    }
}

__global__ __launch_bounds__(256)
void flash_mma_kernel(const float* __restrict__ Q, const float* __restrict__ K,
                      const float* __restrict__ V, float* __restrict__ O)
{
    extern __shared__ __align__(16) float sm[];
    const uint32_t sb = smem_u32(sm);

    const int tid = threadIdx.x;
    const int w = tid >> 5;
    const int lane = tid & 31;
    const int lr = lane >> 2;
    const int lc = lane & 3;

    const int qt = (SS / 128 - 1) - blockIdx.x;
    const int h  = blockIdx.y;
    const int b  = blockIdx.z;
    const int bh = b * HH + h;

    const float* Qg = Q + ((size_t)bh * SS + qt * 128) * HD;
    const float* Kb = K + (size_t)bh * SS * HD;
    const float* Vb = V + (size_t)bh * SS * HD;

    // per-lane ldmatrix byte offsets
    const uint32_t kb_off =
        (( ((lane >> 4) << 3) + (lane & 7) ) * FPAD + (((lane >> 3) & 1) << 2)) * 4;
    const uint32_t p_off =
        ((w * 16 + (lane & 15)) * FPAD + ((lane >> 4) << 2)) * 4;
    const uint32_t qp_base = sb + F_QP * 4;

    // ---- stage Q into smem, then extract scaled fragments (Q pre-rounded;
    //      x0.125 is exact, so no re-round needed) ----
    float* QP = sm + F_QP;
#pragma unroll
    for (int t = 0; t < 8; ++t) {
        int idx = tid + t * 256;
        int row = idx >> 4;
        int c4 = (idx & 15) * 4;
        float4 v = *(const float4*)(Qg + row * HD + c4);
        *(float4*)&QP[row * FPAD + c4] = v;
    }
    __syncthreads();

    uint32_t qa[8][4];
    {
        const float s8 = 0.125f;
        int r = w * 16 + lr;
#pragma unroll
        for (int kk = 0; kk < 8; ++kk) {
            int k0 = kk * 8 + lc;
            qa[kk][0] = __float_as_uint(QP[r * FPAD + k0] * s8);
            qa[kk][1] = __float_as_uint(QP[(r + 8) * FPAD + k0] * s8);
            qa[kk][2] = __float_as_uint(QP[r * FPAD + k0 + 4] * s8);
            qa[kk][3] = __float_as_uint(QP[(r + 8) * FPAD + k0 + 4] * s8);
        }
    }

    float oacc[8][4];
#pragma unroll
    for (int nt = 0; nt < 8; ++nt)
#pragma unroll
        for (int i = 0; i < 4; ++i) oacc[nt][i] = 0.0f;
    float mA = -INFINITY, mB = -INFINITY, lA = 0.0f, lB = 0.0f;

    const int jmax = 2 * qt + 1;

    flash_load_kv(Kb, Vb, tid, sb + F_KS0 * 4, sb + F_VS0 * 4);
    asm volatile("cp.async.commit_group;" ::: "memory");

    float* Pt = QP;

    for (int j = 0; j <= jmax; ++j) {
        __syncthreads();

        if (j + 1 <= jmax) {
            int st = (j + 1) & 1;
            flash_load_kv(Kb + (size_t)(j + 1) * 64 * HD,
                          Vb + (size_t)(j + 1) * 64 * HD, tid,
                          sb + (F_KS0 + st * 64 * FPAD) * 4,
                          sb + (F_VS0 + st * 64 * FPAD) * 4);
        }
        asm volatile("cp.async.commit_group;" ::: "memory");
        asm volatile("cp.async.wait_group 1;" ::: "memory");
        __syncthreads();

        const int st = j & 1;
        const uint32_t ksb = sb + (F_KS0 + st * 64 * FPAD) * 4;
        const float* Vs = sm + F_VS0 + st * 64 * FPAD;

        // ---- S = (Q/8) K^T via ldmatrix ----
        float sacc[8][4];
#pragma unroll
        for (int nt = 0; nt < 8; ++nt)
#pragma unroll
            for (int i = 0; i < 4; ++i) sacc[nt][i] = 0.0f;

#pragma unroll
        for (int kk = 0; kk < 8; ++kk) {
#pragma unroll
            for (int p = 0; p < 4; ++p) {
                uint32_t bf[4];
                LDSM4(bf[0], bf[1], bf[2], bf[3],
                      ksb + kb_off + p * (16 * FPAD * 4) + kk * 32);
                mma_tf32(sacc[2 * p], qa[kk], bf);
                mma_tf32(sacc[2 * p + 1], qa[kk], bf + 2);
            }
        }

        // ---- causal mask ----
        if (j >= 2 * qt) {
            int rowA = qt * 128 + w * 16 + lr;
            int rowB = rowA + 8;
#pragma unroll
            for (int nt = 0; nt < 8; ++nt) {
                int c0 = j * 64 + nt * 8 + 2 * lc;
                int c1 = c0 + 1;
                if (c0 > rowA) sacc[nt][0] = -1.0e30f;
                if (c1 > rowA) sacc[nt][1] = -1.0e30f;
                if (c0 > rowB) sacc[nt][2] = -1.0e30f;
                if (c1 > rowB) sacc[nt][3] = -1.0e30f;
            }
        }

        // ---- online softmax ----
        float mxA = -INFINITY, mxB = -INFINITY;
#pragma unroll
        for (int nt = 0; nt < 8; ++nt) {
            mxA = fmaxf(mxA, fmaxf(sacc[nt][0], sacc[nt][1]));
            mxB = fmaxf(mxB, fmaxf(sacc[nt][2], sacc[nt][3]));
        }
        mxA = fmaxf(mxA, __shfl_xor_sync(0xffffffffu, mxA, 1));
        mxA = fmaxf(mxA, __shfl_xor_sync(0xffffffffu, mxA, 2));
        mxB = fmaxf(mxB, __shfl_xor_sync(0xffffffffu, mxB, 1));
        mxB = fmaxf(mxB, __shfl_xor_sync(0xffffffffu, mxB, 2));

        float mnA = fmaxf(mA, mxA);
        float mnB = fmaxf(mB, mxB);
        float corrA = __expf(mA - mnA);
        float corrB = __expf(mB - mnB);
        mA = mnA; mB = mnB;

        float rsA = 0.0f, rsB = 0.0f;
#pragma unroll
        for (int nt = 0; nt < 8; ++nt) {
            sacc[nt][0] = __expf(sacc[nt][0] - mnA);
            sacc[nt][1] = __expf(sacc[nt][1] - mnA);
            sacc[nt][2] = __expf(sacc[nt][2] - mnB);
            sacc[nt][3] = __expf(sacc[nt][3] - mnB);
            rsA += sacc[nt][0] + sacc[nt][1];
            rsB += sacc[nt][2] + sacc[nt][3];
        }
        rsA += __shfl_xor_sync(0xffffffffu, rsA, 1);
        rsA += __shfl_xor_sync(0xffffffffu, rsA, 2);
        rsB += __shfl_xor_sync(0xffffffffu, rsB, 1);
        rsB += __shfl_xor_sync(0xffffffffu, rsB, 2);
        lA = lA * corrA + rsA;
        lB = lB * corrB + rsB;

#pragma unroll
        for (int nt = 0; nt < 8; ++nt) {
            oacc[nt][0] *= corrA;
            oacc[nt][1] *= corrA;
            oacc[nt][2] *= corrB;
            oacc[nt][3] *= corrB;
        }

        // ---- stage P (tf32 bits) into warp-private smem rows ----
        {
            int rA = w * 16 + lr;
#pragma unroll
            for (int nt = 0; nt < 8; ++nt) {
                int c = nt * 8 + 2 * lc;
                float2 pA, pB;
                pA.x = __uint_as_float(f2tf32(sacc[nt][0]));
                pA.y = __uint_as_float(f2tf32(sacc[nt][1]));
                pB.x = __uint_as_float(f2tf32(sacc[nt][2]));
                pB.y = __uint_as_float(f2tf32(sacc[nt][3]));
                *(float2*)&Pt[rA * FPAD + c] = pA;
                *(float2*)&Pt[(rA + 8) * FPAD + c] = pB;
            }
        }
        __syncwarp();

        // ---- O += P V (P via ldmatrix, V scalar raw bits) ----
#pragma unroll
        for (int kk = 0; kk < 8; ++kk) {
            uint32_t pa[4];
            LDSM4(pa[0], pa[1], pa[2], pa[3], qp_base + p_off + kk * 32);
            int vrow0 = (kk * 8 + lc) * FPAD;
            int vrow1 = vrow0 + 4 * FPAD;
#pragma unroll
            for (int nt = 0; nt < 8; ++nt) {
                int d = nt * 8 + lr;
                uint32_t bf[2];
                bf[0] = __float_as_uint(Vs[vrow0 + d]);
                bf[1] = __float_as_uint(Vs[vrow1 + d]);
                mma_tf32(oacc[nt], pa, bf);
            }
        }
        __syncwarp();
    }

    // ---- epilogue: ctx rounded to tf32 (consumed by the Wo GEMM) ----
    float invA = 1.0f / lA;
    float invB = 1.0f / lB;
    int rowA = qt * 128 + w * 16 + lr;
    float* Og = O + ((size_t)b * SS) * DD + h * HD;
#pragma unroll
    for (int nt = 0; nt < 8; ++nt) {
        int d = nt * 8 + 2 * lc;
        float2 vA = make_float2(roundtf(oacc[nt][0] * invA),
                                roundtf(oacc[nt][1] * invA));
        float2 vB = make_float2(roundtf(oacc[nt][2] * invB),
                                roundtf(oacc[nt][3] * invB));
        *(float2*)&Og[(size_t)rowA * DD + d] = vA;
        *(float2*)&Og[(size_t)(rowA + 8) * DD + d] = vB;
    }
}

// ---------------------------------------------------------------------------
// kernel_launch
// Input order: x, mask, rope_cos, rope_sin, Wq, bq, Wk, bk, Wv, bv, Wo, bo
// ---------------------------------------------------------------------------
extern "C" void kernel_launch(void* const* d_in, const int* in_sizes, int n_in,
                              void* d_out, int out_size)
{
    (void)in_sizes; (void)n_in; (void)out_size;

    const float* x    = (const float*)d_in[0];
    const float* cosb = (const float*)d_in[2];
    const float* sinb = (const float*)d_in[3];
    const float* Wq = (const float*)d_in[4];
    const float* bq = (const float*)d_in[5];
    const float* Wk = (const float*)d_in[6];
    const float* bk = (const float*)d_in[7];
    const float* Wv = (const float*)d_in[8];
    const float* bv = (const float*)d_in[9];
    const float* Wo = (const float*)d_in[10];
    const float* bo = (const float*)d_in[11];
    float* out = (float*)d_out;

    float *Qp, *Kp, *Vp, *Cp, *Xr, *Wr;
    cudaGetSymbolAddress((void**)&Qp, g_Q);
    cudaGetSymbolAddress((void**)&Kp, g_K);
    cudaGetSymbolAddress((void**)&Vp, g_V);
    cudaGetSymbolAddress((void**)&Cp, g_ctx);
    cudaGetSymbolAddress((void**)&Xr, g_Xr);
    cudaGetSymbolAddress((void**)&Wr, g_Wr);

    cudaFuncSetAttribute(gemm_mma_kernel<true, false>,
                         cudaFuncAttributeMaxDynamicSharedMemorySize, GEMM_SMEM);
    cudaFuncSetAttribute(gemm_mma_kernel<true, true>,
                         cudaFuncAttributeMaxDynamicSharedMemorySize, GEMM_SMEM);
    cudaFuncSetAttribute(gemm_mma_kernel<false, false>,
                         cudaFuncAttributeMaxDynamicSharedMemorySize, GEMM_SMEM);
    cudaFuncSetAttribute(flash_mma_kernel,
                         cudaFuncAttributeMaxDynamicSharedMemorySize, FLASH_SMEM);

    // --- pre-round inputs to tf32 ---
    round_kernel<<<(MROWS * DD / 4 + 255) / 256, 256>>>(x, Xr, MROWS * DD / 4);
    round_kernel<<<(DD * DD / 4 + 255) / 256, 256>>>(Wq, Wr + 0 * DD * DD, DD * DD / 4);
    round_kernel<<<(DD * DD / 4 + 255) / 256, 256>>>(Wk, Wr + 1 * DD * DD, DD * DD / 4);
    round_kernel<<<(DD * DD / 4 + 255) / 256, 256>>>(Wv, Wr + 2 * DD * DD, DD * DD / 4);
    round_kernel<<<(DD * DD / 4 + 255) / 256, 256>>>(Wo, Wr + 3 * DD * DD, DD * DD / 4);

    dim3 ggrid(DD / 128, MROWS / 128);   // (8, 64) = 512 CTAs

    gemm_mma_kernel<true, false><<<ggrid, 256, GEMM_SMEM>>>(Xr, Wr + 0 * DD * DD, bq, Qp);
    gemm_mma_kernel<true, false><<<ggrid, 256, GEMM_SMEM>>>(Xr, Wr + 1 * DD * DD, bk, Kp);
    gemm_mma_kernel<true, true><<<ggrid, 256, GEMM_SMEM>>>(Xr, Wr + 2 * DD * DD, bv, Vp);

    int rope_threads = BB * HH * SS * 32;
    rope_kernel<<<rope_threads / 256, 256>>>(Qp, cosb, sinb);
    rope_kernel<<<rope_threads / 256, 256>>>(Kp, cosb, sinb);

    flash_mma_kernel<<<dim3(SS / 128, HH, BB), 256, FLASH_SMEM>>>(Qp, Kp, Vp, Cp);

    gemm_mma_kernel<false, false><<<ggrid, 256, GEMM_SMEM>>>(Cp, Wr + 3 * DD * DD, bo, out);
}

// round 7
// speedup vs baseline: 1.4121x; 1.4121x over previous
#include <cuda_runtime.h>
#include <math.h>
#include <stdint.h>

// Problem constants
#define BB 4
#define HH 16
#define SS 2048
#define DD 1024
#define HD 64
#define MROWS (BB * SS)   // 8192

// ---------------------------------------------------------------------------
// Scratch (no allocations allowed -> __device__ globals)
// ---------------------------------------------------------------------------
__device__ float g_Q[BB * HH * SS * HD];
__device__ float g_K[BB * HH * SS * HD];
__device__ float g_V[BB * HH * SS * HD];
__device__ float g_ctx[BB * SS * DD];
__device__ float g_Xr[MROWS * DD];        // tf32-rounded x
__device__ float g_Wr[4 * DD * DD];       // tf32-rounded Wq,Wk,Wv,Wo

// ---------------------------------------------------------------------------
// helpers
// ---------------------------------------------------------------------------
__device__ __forceinline__ uint32_t smem_u32(const void* p) {
    uint32_t a;
    asm("{ .reg .u64 t; cvta.to.shared.u64 t, %1; cvt.u32.u64 %0, t; }"
        : "=r"(a) : "l"(p));
    return a;
}

__device__ __forceinline__ uint32_t f2tf32(float f) {
    uint32_t u;
    asm("cvt.rna.tf32.f32 %0, %1;" : "=r"(u) : "f"(f));
    return u;
}

__device__ __forceinline__ float roundtf(float f) {
    return __uint_as_float(f2tf32(f));
}

// mma.sync m16n8k8 tf32, fp32 accumulate (in place on d)
__device__ __forceinline__ void mma_tf32(float d[4], const uint32_t a[4],
                                         const uint32_t b[2]) {
    asm volatile(
        "mma.sync.aligned.m16n8k8.row.col.f32.tf32.tf32.f32 "
        "{%0,%1,%2,%3}, {%4,%5,%6,%7}, {%8,%9}, {%0,%1,%2,%3};"
        : "+f"(d[0]), "+f"(d[1]), "+f"(d[2]), "+f"(d[3])
        : "r"(a[0]), "r"(a[1]), "r"(a[2]), "r"(a[3]), "r"(b[0]), "r"(b[1]));
}

// ---------------------------------------------------------------------------
// Elementwise tf32 pre-round (float4 vectorized)
// ---------------------------------------------------------------------------
__global__ void round_kernel(const float* __restrict__ in,
                             float* __restrict__ out, int n4)
{
    int i = blockIdx.x * blockDim.x + threadIdx.x;
    if (i < n4) {
        float4 v = ((const float4*)in)[i];
        v.x = roundtf(v.x);
        v.y = roundtf(v.y);
        v.z = roundtf(v.z);
        v.w = roundtf(v.w);
        ((float4*)out)[i] = v;
    }
}

// ===========================================================================
// tf32 mma.sync GEMM (inputs pre-rounded -> raw-bit fragment loads).
// Y[m][n] = sum_k X[m][k]*W[n][k] + bias[n].
// CTA tile 128x128, BK=32, 8 warps (4m x 2n), warp tile 32x64.
// 3-stage cp.async ring. Smem padded to 36 floats/row.
// ===========================================================================
#define GBK 32
#define GPAD 36
#define GSTAGE_FLOATS (128 * GPAD)
#define GSTAGE_BYTES  (2 * GSTAGE_FLOATS * 4)
#define GNSTAGE 3
#define GEMM_SMEM (GNSTAGE * GSTAGE_BYTES)

__device__ __forceinline__ void gemm_issue_loads(
    const float* __restrict__ X, const float* __restrict__ W,
    int m0, int n0, int tid, uint32_t stage_addr, int k0)
{
#pragma unroll
    for (int t = 0; t < 4; ++t) {
        int idx = tid + t * 256;
        int row = idx >> 3;
        int c = idx & 7;
        const float* src = X + (size_t)(m0 + row) * 1024 + k0 + c * 4;
        uint32_t dst = stage_addr + row * 144 + c * 16;
        asm volatile("cp.async.cg.shared.global [%0], [%1], 16;"
                     :: "r"(dst), "l"(src));
    }
#pragma unroll
    for (int t = 0; t < 4; ++t) {
        int idx = tid + t * 256;
        int row = idx >> 3;
        int c = idx & 7;
        const float* src = W + (size_t)(n0 + row) * 1024 + k0 + c * 4;
        uint32_t dst = stage_addr + 18432 + row * 144 + c * 16;
        asm volatile("cp.async.cg.shared.global [%0], [%1], 16;"
                     :: "r"(dst), "l"(src));
    }
}

template <bool BHSD, bool ROUND>
__global__ __launch_bounds__(256)
void gemm_mma_kernel(const float* __restrict__ X, const float* __restrict__ W,
                     const float* __restrict__ bias, float* __restrict__ Y)
{
    extern __shared__ __align__(16) float smem[];
    const uint32_t sb = smem_u32(smem);
    const int tid = threadIdx.x;
    const int wid = tid >> 5;
    const int lane = tid & 31;
    const int wm = wid >> 1;
    const int wn = wid & 1;
    const int m0 = blockIdx.y * 128;
    const int n0 = blockIdx.x * 128;

    const int lr = lane >> 2;
    const int lc = lane & 3;

    float acc[2][8][4];
#pragma unroll
    for (int mt = 0; mt < 2; ++mt)
#pragma unroll
        for (int nt = 0; nt < 8; ++nt)
#pragma unroll
            for (int i = 0; i < 4; ++i) acc[mt][nt][i] = 0.0f;

    gemm_issue_loads(X, W, m0, n0, tid, sb + 0 * GSTAGE_BYTES, 0);
    asm volatile("cp.async.commit_group;" ::: "memory");
    gemm_issue_loads(X, W, m0, n0, tid, sb + 1 * GSTAGE_BYTES, GBK);
    asm volatile("cp.async.commit_group;" ::: "memory");

    const int NK = 1024 / GBK;
    for (int s = 0; s < NK; ++s) {
        int t = s + 2;
        if (t < NK)
            gemm_issue_loads(X, W, m0, n0, tid,
                             sb + (t % GNSTAGE) * GSTAGE_BYTES, t * GBK);
        asm volatile("cp.async.commit_group;" ::: "memory");
        asm volatile("cp.async.wait_group 2;" ::: "memory");
        __syncthreads();

        const float* As = smem + (s % GNSTAGE) * (2 * GSTAGE_FLOATS);
        const float* Bs = As + GSTAGE_FLOATS;

#pragma unroll
        for (int kk = 0; kk < 4; ++kk) {
            int k0 = kk * 8 + lc;
            uint32_t af[2][4];
#pragma unroll
            for (int mt = 0; mt < 2; ++mt) {
                int r = wm * 32 + mt * 16 + lr;
                af[mt][0] = __float_as_uint(As[r * GPAD + k0]);
                af[mt][1] = __float_as_uint(As[(r + 8) * GPAD + k0]);
                af[mt][2] = __float_as_uint(As[r * GPAD + k0 + 4]);
                af[mt][3] = __float_as_uint(As[(r + 8) * GPAD + k0 + 4]);
            }
            uint32_t bf[8][2];
#pragma unroll
            for (int nt = 0; nt < 8; ++nt) {
                int n = wn * 64 + nt * 8 + lr;
                bf[nt][0] = __float_as_uint(Bs[n * GPAD + k0]);
                bf[nt][1] = __float_as_uint(Bs[n * GPAD + k0 + 4]);
            }
#pragma unroll
            for (int mt = 0; mt < 2; ++mt)
#pragma unroll
                for (int nt = 0; nt < 8; ++nt)
                    mma_tf32(acc[mt][nt], af[mt], bf[nt]);
        }
        __syncthreads();
    }

#pragma unroll
    for (int nt = 0; nt < 8; ++nt) {
        int ncol = n0 + wn * 64 + nt * 8 + 2 * lc;
        float b0 = __ldg(&bias[ncol]);
        float b1 = __ldg(&bias[ncol + 1]);
#pragma unroll
        for (int mt = 0; mt < 2; ++mt) {
            int m = m0 + wm * 32 + mt * 16 + lr;
            float2 v0 = make_float2(acc[mt][nt][0] + b0, acc[mt][nt][1] + b1);
            float2 v1 = make_float2(acc[mt][nt][2] + b0, acc[mt][nt][3] + b1);
            if (ROUND) {
                v0.x = roundtf(v0.x); v0.y = roundtf(v0.y);
                v1.x = roundtf(v1.x); v1.y = roundtf(v1.y);
            }
            if (BHSD) {
                int b   = m >> 11;
                int sq  = m & 2047;
                int h   = ncol >> 6;
                int dd  = ncol & 63;
                float* d0 = &Y[(((size_t)(b * HH + h) * SS) + sq) * HD + dd];
                *(float2*)d0 = v0;
                int m8 = m + 8;
                int b8 = m8 >> 11;
                int sq8 = m8 & 2047;
                float* d1 = &Y[(((size_t)(b8 * HH + h) * SS) + sq8) * HD + dd];
                *(float2*)d1 = v1;
            } else {
                *(float2*)&Y[(size_t)m * DD + ncol] = v0;
                *(float2*)&Y[(size_t)(m + 8) * DD + ncol] = v1;
            }
        }
    }
}

// ---------------------------------------------------------------------------
// RoPE in-place on [B, H, S, 64]; outputs rounded to tf32.
// ---------------------------------------------------------------------------
__global__ void rope_kernel(float* __restrict__ P,
                            const float* __restrict__ cosb,
                            const float* __restrict__ sinb)
{
    int idx = blockIdx.x * blockDim.x + threadIdx.x;
    int i = idx & 31;
    int bhs = idx >> 5;
    int s = bhs & (SS - 1);
    float* p = P + (size_t)bhs * HD;
    float x0 = p[i];
    float x1 = p[i + 32];
    float c  = cosb[s * HD + i];
    float sn = sinb[s * HD + i];
    p[i]      = roundtf(x0 * c - x1 * sn);
    p[i + 32] = roundtf(x1 * c + x0 * sn);
}

// ===========================================================================
// Flash attention via mma.sync tf32 (Q/K/V pre-rounded -> raw-bit loads).
// BM=128 (8 warps x 16 rows), BN=64 per iteration, HD=64.
// ===========================================================================
#define FPAD 68
#define F_KS0 0
#define F_VS0 (2 * 64 * FPAD)
#define F_QP  (4 * 64 * FPAD)
#define FLASH_SMEM ((4 * 64 * FPAD + 128 * FPAD) * 4)   // 104448 bytes

__device__ __forceinline__ void flash_load_kv(
    const float* __restrict__ Kg, const float* __restrict__ Vg,
    int tid, uint32_t ks_addr, uint32_t vs_addr)
{
#pragma unroll
    for (int t = 0; t < 4; ++t) {
        int idx = tid + t * 256;
        int row = idx >> 4;
        int c4 = idx & 15;
        const float* srcK = Kg + row * HD + c4 * 4;
        const float* srcV = Vg + row * HD + c4 * 4;
        uint32_t dK = ks_addr + row * (FPAD * 4) + c4 * 16;
        uint32_t dV = vs_addr + row * (FPAD * 4) + c4 * 16;
        asm volatile("cp.async.cg.shared.global [%0], [%1], 16;" :: "r"(dK), "l"(srcK));
        asm volatile("cp.async.cg.shared.global [%0], [%1], 16;" :: "r"(dV), "l"(srcV));
    }
}

__global__ __launch_bounds__(256)
void flash_mma_kernel(const float* __restrict__ Q, const float* __restrict__ K,
                      const float* __restrict__ V, float* __restrict__ O)
{
    extern __shared__ __align__(16) float sm[];
    const uint32_t sb = smem_u32(sm);

    const int tid = threadIdx.x;
    const int w = tid >> 5;
    const int lane = tid & 31;
    const int lr = lane >> 2;
    const int lc = lane & 3;

    const int qt = (SS / 128 - 1) - blockIdx.x;
    const int h  = blockIdx.y;
    const int b  = blockIdx.z;
    const int bh = b * HH + h;

    const float* Qg = Q + ((size_t)bh * SS + qt * 128) * HD;
    const float* Kb = K + (size_t)bh * SS * HD;
    const float* Vb = V + (size_t)bh * SS * HD;

    // ---- stage Q into smem, then extract scaled fragments (Q pre-rounded;
    //      x0.125 is exact in tf32, so no re-round needed) ----
    float* QP = sm + F_QP;
#pragma unroll
    for (int t = 0; t < 8; ++t) {
        int idx = tid + t * 256;
        int row = idx >> 4;
        int c4 = (idx & 15) * 4;
        float4 v = *(const float4*)(Qg + row * HD + c4);
        *(float4*)&QP[row * FPAD + c4] = v;
    }
    __syncthreads();

    uint32_t qa[8][4];
    {
        const float s8 = 0.125f;
        int r = w * 16 + lr;
#pragma unroll
        for (int kk = 0; kk < 8; ++kk) {
            int k0 = kk * 8 + lc;
            qa[kk][0] = __float_as_uint(QP[r * FPAD + k0] * s8);
            qa[kk][1] = __float_as_uint(QP[(r + 8) * FPAD + k0] * s8);
            qa[kk][2] = __float_as_uint(QP[r * FPAD + k0 + 4] * s8);
            qa[kk][3] = __float_as_uint(QP[(r + 8) * FPAD + k0 + 4] * s8);
        }
    }

    float oacc[8][4];
#pragma unroll
    for (int nt = 0; nt < 8; ++nt)
#pragma unroll
        for (int i = 0; i < 4; ++i) oacc[nt][i] = 0.0f;
    float mA = -INFINITY, mB = -INFINITY, lA = 0.0f, lB = 0.0f;

    const int jmax = 2 * qt + 1;

    flash_load_kv(Kb, Vb, tid, sb + F_KS0 * 4, sb + F_VS0 * 4);
    asm volatile("cp.async.commit_group;" ::: "memory");

    float* Pt = QP;

    for (int j = 0; j <= jmax; ++j) {
        __syncthreads();

        if (j + 1 <= jmax) {
            int st = (j + 1) & 1;
            flash_load_kv(Kb + (size_t)(j + 1) * 64 * HD,
                          Vb + (size_t)(j + 1) * 64 * HD, tid,
                          sb + (F_KS0 + st * 64 * FPAD) * 4,
                          sb + (F_VS0 + st * 64 * FPAD) * 4);
        }
        asm volatile("cp.async.commit_group;" ::: "memory");
        asm volatile("cp.async.wait_group 1;" ::: "memory");
        __syncthreads();

        const int st = j & 1;
        const float* Ks = sm + F_KS0 + st * 64 * FPAD;
        const float* Vs = sm + F_VS0 + st * 64 * FPAD;

        // ---- S = (Q/8) K^T (raw-bit K loads) ----
        float sacc[8][4];
#pragma unroll
        for (int nt = 0; nt < 8; ++nt)
#pragma unroll
            for (int i = 0; i < 4; ++i) sacc[nt][i] = 0.0f;

#pragma unroll
        for (int kk = 0; kk < 8; ++kk) {
            int k0 = kk * 8 + lc;
#pragma unroll
            for (int nt = 0; nt < 8; ++nt) {
                int c = nt * 8 + lr;
                uint32_t bf[2];
                bf[0] = __float_as_uint(Ks[c * FPAD + k0]);
                bf[1] = __float_as_uint(Ks[c * FPAD + k0 + 4]);
                mma_tf32(sacc[nt], qa[kk], bf);
            }
        }

        // ---- causal mask ----
        if (j >= 2 * qt) {
            int rowA = qt * 128 + w * 16 + lr;
            int rowB = rowA + 8;
#pragma unroll
            for (int nt = 0; nt < 8; ++nt) {
                int c0 = j * 64 + nt * 8 + 2 * lc;
                int c1 = c0 + 1;
                if (c0 > rowA) sacc[nt][0] = -1.0e30f;
                if (c1 > rowA) sacc[nt][1] = -1.0e30f;
                if (c0 > rowB) sacc[nt][2] = -1.0e30f;
                if (c1 > rowB) sacc[nt][3] = -1.0e30f;
            }
        }

        // ---- online softmax ----
        float mxA = -INFINITY, mxB = -INFINITY;
#pragma unroll
        for (int nt = 0; nt < 8; ++nt) {
            mxA = fmaxf(mxA, fmaxf(sacc[nt][0], sacc[nt][1]));
            mxB = fmaxf(mxB, fmaxf(sacc[nt][2], sacc[nt][3]));
        }
        mxA = fmaxf(mxA, __shfl_xor_sync(0xffffffffu, mxA, 1));
        mxA = fmaxf(mxA, __shfl_xor_sync(0xffffffffu, mxA, 2));
        mxB = fmaxf(mxB, __shfl_xor_sync(0xffffffffu, mxB, 1));
        mxB = fmaxf(mxB, __shfl_xor_sync(0xffffffffu, mxB, 2));

        float mnA = fmaxf(mA, mxA);
        float mnB = fmaxf(mB, mxB);
        float corrA = __expf(mA - mnA);
        float corrB = __expf(mB - mnB);
        mA = mnA; mB = mnB;

        float rsA = 0.0f, rsB = 0.0f;
#pragma unroll
        for (int nt = 0; nt < 8; ++nt) {
            sacc[nt][0] = __expf(sacc[nt][0] - mnA);
            sacc[nt][1] = __expf(sacc[nt][1] - mnA);
            sacc[nt][2] = __expf(sacc[nt][2] - mnB);
            sacc[nt][3] = __expf(sacc[nt][3] - mnB);
            rsA += sacc[nt][0] + sacc[nt][1];
            rsB += sacc[nt][2] + sacc[nt][3];
        }
        rsA += __shfl_xor_sync(0xffffffffu, rsA, 1);
        rsA += __shfl_xor_sync(0xffffffffu, rsA, 2);
        rsB += __shfl_xor_sync(0xffffffffu, rsB, 1);
        rsB += __shfl_xor_sync(0xffffffffu, rsB, 2);
        lA = lA * corrA + rsA;
        lB = lB * corrB + rsB;

#pragma unroll
        for (int nt = 0; nt < 8; ++nt) {
            oacc[nt][0] *= corrA;
            oacc[nt][1] *= corrA;
            oacc[nt][2] *= corrB;
            oacc[nt][3] *= corrB;
        }

        // ---- stage P (tf32 bits) into warp-private smem rows ----
        {
            int rA = w * 16 + lr;
#pragma unroll
            for (int nt = 0; nt < 8; ++nt) {
                int c = nt * 8 + 2 * lc;
                float2 pA, pB;
                pA.x = __uint_as_float(f2tf32(sacc[nt][0]));
                pA.y = __uint_as_float(f2tf32(sacc[nt][1]));
                pB.x = __uint_as_float(f2tf32(sacc[nt][2]));
                pB.y = __uint_as_float(f2tf32(sacc[nt][3]));
                *(float2*)&Pt[rA * FPAD + c] = pA;
                *(float2*)&Pt[(rA + 8) * FPAD + c] = pB;
            }
        }
        __syncwarp();

        // ---- O += P V (raw-bit loads everywhere) ----
#pragma unroll
        for (int kk = 0; kk < 8; ++kk) {
            int k0 = kk * 8 + lc;
            int r = w * 16 + lr;
            uint32_t pa[4];
            pa[0] = __float_as_uint(Pt[r * FPAD + k0]);
            pa[1] = __float_as_uint(Pt[(r + 8) * FPAD + k0]);
            pa[2] = __float_as_uint(Pt[r * FPAD + k0 + 4]);
            pa[3] = __float_as_uint(Pt[(r + 8) * FPAD + k0 + 4]);
#pragma unroll
            for (int nt = 0; nt < 8; ++nt) {
                int d = nt * 8 + lr;
                uint32_t bf[2];
                bf[0] = __float_as_uint(Vs[(kk * 8 + lc) * FPAD + d]);
                bf[1] = __float_as_uint(Vs[(kk * 8 + lc + 4) * FPAD + d]);
                mma_tf32(oacc[nt], pa, bf);
            }
        }
        __syncwarp();
    }

    // ---- epilogue: ctx rounded to tf32 (consumed by the Wo GEMM) ----
    float invA = 1.0f / lA;
    float invB = 1.0f / lB;
    int rowA = qt * 128 + w * 16 + lr;
    float* Og = O + ((size_t)b * SS) * DD + h * HD;
#pragma unroll
    for (int nt = 0; nt < 8; ++nt) {
        int d = nt * 8 + 2 * lc;
        float2 vA = make_float2(roundtf(oacc[nt][0] * invA),
                                roundtf(oacc[nt][1] * invA));
        float2 vB = make_float2(roundtf(oacc[nt][2] * invB),
                                roundtf(oacc[nt][3] * invB));
        *(float2*)&Og[(size_t)rowA * DD + d] = vA;
        *(float2*)&Og[(size_t)(rowA + 8) * DD + d] = vB;
    }
}

// ---------------------------------------------------------------------------
// kernel_launch
// Input order: x, mask, rope_cos, rope_sin, Wq, bq, Wk, bk, Wv, bv, Wo, bo
// ---------------------------------------------------------------------------
extern "C" void kernel_launch(void* const* d_in, const int* in_sizes, int n_in,
                              void* d_out, int out_size)
{
    (void)in_sizes; (void)n_in; (void)out_size;

    const float* x    = (const float*)d_in[0];
    const float* cosb = (const float*)d_in[2];
    const float* sinb = (const float*)d_in[3];
    const float* Wq = (const float*)d_in[4];
    const float* bq = (const float*)d_in[5];
    const float* Wk = (const float*)d_in[6];
    const float* bk = (const float*)d_in[7];
    const float* Wv = (const float*)d_in[8];
    const float* bv = (const float*)d_in[9];
    const float* Wo = (const float*)d_in[10];
    const float* bo = (const float*)d_in[11];
    float* out = (float*)d_out;

    float *Qp, *Kp, *Vp, *Cp, *Xr, *Wr;
    cudaGetSymbolAddress((void**)&Qp, g_Q);
    cudaGetSymbolAddress((void**)&Kp, g_K);
    cudaGetSymbolAddress((void**)&Vp, g_V);
    cudaGetSymbolAddress((void**)&Cp, g_ctx);
    cudaGetSymbolAddress((void**)&Xr, g_Xr);
    cudaGetSymbolAddress((void**)&Wr, g_Wr);

    cudaFuncSetAttribute(gemm_mma_kernel<true, false>,
                         cudaFuncAttributeMaxDynamicSharedMemorySize, GEMM_SMEM);
    cudaFuncSetAttribute(gemm_mma_kernel<true, true>,
                         cudaFuncAttributeMaxDynamicSharedMemorySize, GEMM_SMEM);
    cudaFuncSetAttribute(gemm_mma_kernel<false, false>,
                         cudaFuncAttributeMaxDynamicSharedMemorySize, GEMM_SMEM);
    cudaFuncSetAttribute(flash_mma_kernel,
                         cudaFuncAttributeMaxDynamicSharedMemorySize, FLASH_SMEM);

    // --- pre-round inputs to tf32 ---
    round_kernel<<<(MROWS * DD / 4 + 255) / 256, 256>>>(x, Xr, MROWS * DD / 4);
    round_kernel<<<(DD * DD / 4 + 255) / 256, 256>>>(Wq, Wr + 0 * DD * DD, DD * DD / 4);
    round_kernel<<<(DD * DD / 4 + 255) / 256, 256>>>(Wk, Wr + 1 * DD * DD, DD * DD / 4);
    round_kernel<<<(DD * DD / 4 + 255) / 256, 256>>>(Wv, Wr + 2 * DD * DD, DD * DD / 4);
    round_kernel<<<(DD * DD / 4 + 255) / 256, 256>>>(Wo, Wr + 3 * DD * DD, DD * DD / 4);

    dim3 ggrid(DD / 128, MROWS / 128);   // (8, 64) = 512 CTAs

    gemm_mma_kernel<true, false><<<ggrid, 256, GEMM_SMEM>>>(Xr, Wr + 0 * DD * DD, bq, Qp);
    gemm_mma_kernel<true, false><<<ggrid, 256, GEMM_SMEM>>>(Xr, Wr + 1 * DD * DD, bk, Kp);
    gemm_mma_kernel<true, true><<<ggrid, 256, GEMM_SMEM>>>(Xr, Wr + 2 * DD * DD, bv, Vp);

    int rope_threads = BB * HH * SS * 32;
    rope_kernel<<<rope_threads / 256, 256>>>(Qp, cosb, sinb);
    rope_kernel<<<rope_threads / 256, 256>>>(Kp, cosb, sinb);

    flash_mma_kernel<<<dim3(SS / 128, HH, BB), 256, FLASH_SMEM>>>(Qp, Kp, Vp, Cp);

    gemm_mma_kernel<false, false><<<ggrid, 256, GEMM_SMEM>>>(Cp, Wr + 3 * DD * DD, bo, out);
}

// round 8
// speedup vs baseline: 2.6563x; 1.8811x over previous
#include <cuda_runtime.h>
#include <cuda_fp16.h>
#include <math.h>
#include <stdint.h>

// Problem constants
#define BB 4
#define HH 16
#define SS 2048
#define DD 1024
#define HD 64
#define MROWS (BB * SS)   // 8192

// ---------------------------------------------------------------------------
// Scratch (no allocations allowed -> __device__ globals)
// ---------------------------------------------------------------------------
__device__ __half g_Qh[BB * HH * SS * HD];
__device__ __half g_Kh[BB * HH * SS * HD];
__device__ __half g_Vt[BB * HH * HD * SS];   // [b,h,d,s] transposed
__device__ __half g_ctx[BB * SS * DD];
__device__ __half g_Xh[MROWS * DD];
__device__ __half g_Wh[4 * DD * DD];

// ---------------------------------------------------------------------------
// helpers
// ---------------------------------------------------------------------------
__device__ __forceinline__ uint32_t smem_u32(const void* p) {
    uint32_t a;
    asm("{ .reg .u64 t; cvta.to.shared.u64 t, %1; cvt.u32.u64 %0, t; }"
        : "=r"(a) : "l"(p));
    return a;
}

// mma.sync m16n8k16 fp16 in, fp32 accumulate (in place on d)
__device__ __forceinline__ void mma_f16(float d[4], const uint32_t a[4],
                                        const uint32_t b[2]) {
    asm volatile(
        "mma.sync.aligned.m16n8k16.row.col.f32.f16.f16.f32 "
        "{%0,%1,%2,%3}, {%4,%5,%6,%7}, {%8,%9}, {%0,%1,%2,%3};"
        : "+f"(d[0]), "+f"(d[1]), "+f"(d[2]), "+f"(d[3])
        : "r"(a[0]), "r"(a[1]), "r"(a[2]), "r"(a[3]), "r"(b[0]), "r"(b[1]));
}

// ---------------------------------------------------------------------------
// fp32 -> fp16 convert (float4 -> 4 halves)
// ---------------------------------------------------------------------------
__global__ void cvt_kernel(const float* __restrict__ in,
                           __half* __restrict__ out, int n4)
{
    int i = blockIdx.x * blockDim.x + threadIdx.x;
    if (i < n4) {
        float4 v = ((const float4*)in)[i];
        __half2 h0 = __floats2half2_rn(v.x, v.y);
        __half2 h1 = __floats2half2_rn(v.z, v.w);
        ((__half2*)out)[2 * i]     = h0;
        ((__half2*)out)[2 * i + 1] = h1;
    }
}

// ===========================================================================
// fp16 mma.sync GEMM: Y[m][n] = sum_k X[m][k]*W[n][k] + bias[n]
// M=8192, N=1024, K=1024. CTA tile 128x128, BK=32 halves.
// 8 warps (4m x 2n), warp tile 32x64. 3-stage cp.async ring.
// Smem rows padded to 40 halves (80B) -> conflict-free scalar u32 frag loads.
// OUT: 0 = [B,H,S,hd] half (Q/K), 1 = [B,H,hd,S] half (V transposed),
//      2 = flat fp32 (final output)
// ===========================================================================
#define GBK 32
#define GPADH 40
#define GSTAGE_BYTES (2 * 128 * GPADH * 2)   // 20480
#define GNSTAGE 3
#define GEMM_SMEM (GNSTAGE * GSTAGE_BYTES)   // 61440

__device__ __forceinline__ void gemm_issue_loads(
    const __half* __restrict__ X, const __half* __restrict__ W,
    int m0, int n0, int tid, uint32_t stage_addr, int k0)
{
    // A: 128 rows x 32 halves (64B = 4 x 16B chunks per row)
#pragma unroll
    for (int t = 0; t < 2; ++t) {
        int idx = tid + t * 256;       // 0..511
        int row = idx >> 2;
        int c = idx & 3;
        const __half* src = X + (size_t)(m0 + row) * 1024 + k0 + c * 8;
        uint32_t dst = stage_addr + row * (GPADH * 2) + c * 16;
        asm volatile("cp.async.cg.shared.global [%0], [%1], 16;"
                     :: "r"(dst), "l"(src));
    }
#pragma unroll
    for (int t = 0; t < 2; ++t) {
        int idx = tid + t * 256;
        int row = idx >> 2;
        int c = idx & 3;
        const __half* src = W + (size_t)(n0 + row) * 1024 + k0 + c * 8;
        uint32_t dst = stage_addr + 128 * (GPADH * 2) + row * (GPADH * 2) + c * 16;
        asm volatile("cp.async.cg.shared.global [%0], [%1], 16;"
                     :: "r"(dst), "l"(src));
    }
}

template <int OUT>
__global__ __launch_bounds__(256, 2)
void gemm_h_kernel(const __half* __restrict__ X, const __half* __restrict__ W,
                   const float* __restrict__ bias, void* __restrict__ Yv)
{
    extern __shared__ __align__(16) __half smem[];
    const uint32_t sb = smem_u32(smem);
    const int tid = threadIdx.x;
    const int wid = tid >> 5;
    const int lane = tid & 31;
    const int wm = wid >> 1;
    const int wn = wid & 1;
    const int m0 = blockIdx.y * 128;
    const int n0 = blockIdx.x * 128;

    const int lr = lane >> 2;       // 0..7
    const int lc = lane & 3;        // 0..3

    float acc[2][8][4];
#pragma unroll
    for (int mt = 0; mt < 2; ++mt)
#pragma unroll
        for (int nt = 0; nt < 8; ++nt)
#pragma unroll
            for (int i = 0; i < 4; ++i) acc[mt][nt][i] = 0.0f;

    gemm_issue_loads(X, W, m0, n0, tid, sb + 0 * GSTAGE_BYTES, 0);
    asm volatile("cp.async.commit_group;" ::: "memory");
    gemm_issue_loads(X, W, m0, n0, tid, sb + 1 * GSTAGE_BYTES, GBK);
    asm volatile("cp.async.commit_group;" ::: "memory");

    const int NK = 1024 / GBK;   // 32
    for (int s = 0; s < NK; ++s) {
        int t = s + 2;
        if (t < NK)
            gemm_issue_loads(X, W, m0, n0, tid,
                             sb + (t % GNSTAGE) * GSTAGE_BYTES, t * GBK);
        asm volatile("cp.async.commit_group;" ::: "memory");
        asm volatile("cp.async.wait_group 2;" ::: "memory");
        __syncthreads();

        const __half* As = smem + (s % GNSTAGE) * (GSTAGE_BYTES / 2);
        const __half* Bs = As + 128 * GPADH;

#pragma unroll
        for (int kk = 0; kk < 2; ++kk) {     // 2 x k16
            int k0 = kk * 16 + 2 * lc;
            uint32_t af[2][4];
#pragma unroll
            for (int mt = 0; mt < 2; ++mt) {
                int r = wm * 32 + mt * 16 + lr;
                af[mt][0] = *(const uint32_t*)&As[r * GPADH + k0];
                af[mt][1] = *(const uint32_t*)&As[(r + 8) * GPADH + k0];
                af[mt][2] = *(const uint32_t*)&As[r * GPADH + k0 + 8];
                af[mt][3] = *(const uint32_t*)&As[(r + 8) * GPADH + k0 + 8];
            }
            uint32_t bf[8][2];
#pragma unroll
            for (int nt = 0; nt < 8; ++nt) {
                int n = wn * 64 + nt * 8 + lr;
                bf[nt][0] = *(const uint32_t*)&Bs[n * GPADH + k0];
                bf[nt][1] = *(const uint32_t*)&Bs[n * GPADH + k0 + 8];
            }
#pragma unroll
            for (int mt = 0; mt < 2; ++mt)
#pragma unroll
                for (int nt = 0; nt < 8; ++nt)
                    mma_f16(acc[mt][nt], af[mt], bf[nt]);
        }
        __syncthreads();
    }

    // epilogue
#pragma unroll
    for (int nt = 0; nt < 8; ++nt) {
        int ncol = n0 + wn * 64 + nt * 8 + 2 * lc;
        float b0 = __ldg(&bias[ncol]);
        float b1 = __ldg(&bias[ncol + 1]);
#pragma unroll
        for (int mt = 0; mt < 2; ++mt) {
            int m = m0 + wm * 32 + mt * 16 + lr;
            float v00 = acc[mt][nt][0] + b0, v01 = acc[mt][nt][1] + b1;
            float v10 = acc[mt][nt][2] + b0, v11 = acc[mt][nt][3] + b1;
            int b   = m >> 11;
            int sq  = m & 2047;
            int h   = ncol >> 6;
            int dd  = ncol & 63;
            int bh  = b * HH + h;
            if (OUT == 0) {          // [B,H,S,hd] half
                __half* Y = (__half*)Yv;
                *(__half2*)&Y[((size_t)bh * SS + sq) * HD + dd] =
                    __floats2half2_rn(v00, v01);
                *(__half2*)&Y[((size_t)bh * SS + sq + 8) * HD + dd] =
                    __floats2half2_rn(v10, v11);
            } else if (OUT == 1) {   // [B,H,hd,S] half (V transposed)
                __half* Y = (__half*)Yv;
                Y[((size_t)bh * HD + dd) * SS + sq]     = __float2half_rn(v00);
                Y[((size_t)bh * HD + dd + 1) * SS + sq] = __float2half_rn(v01);
                Y[((size_t)bh * HD + dd) * SS + sq + 8]     = __float2half_rn(v10);
                Y[((size_t)bh * HD + dd + 1) * SS + sq + 8] = __float2half_rn(v11);
            } else {                 // flat fp32
                float* Y = (float*)Yv;
                *(float2*)&Y[(size_t)m * DD + ncol] = make_float2(v00, v01);
                *(float2*)&Y[(size_t)(m + 8) * DD + ncol] = make_float2(v10, v11);
            }
        }
    }
}

// ---------------------------------------------------------------------------
// RoPE in-place on half [B,H,S,64]; optional extra scale (1/8 folded into Q).
// ---------------------------------------------------------------------------
template <bool SCALE>
__global__ void rope_h_kernel(__half* __restrict__ P,
                              const float* __restrict__ cosb,
                              const float* __restrict__ sinb)
{
    int idx = blockIdx.x * blockDim.x + threadIdx.x;
    int i = idx & 31;
    int bhs = idx >> 5;
    int s = bhs & (SS - 1);
    __half* p = P + (size_t)bhs * HD;
    float x0 = __half2float(p[i]);
    float x1 = __half2float(p[i + 32]);
    float c  = cosb[s * HD + i];
    float sn = sinb[s * HD + i];
    float y0 = x0 * c - x1 * sn;
    float y1 = x1 * c + x0 * sn;
    if (SCALE) { y0 *= 0.125f; y1 *= 0.125f; }
    p[i]      = __float2half_rn(y0);
    p[i + 32] = __float2half_rn(y1);
}

// ===========================================================================
// Flash attention via mma.sync fp16 (Q pre-scaled by 1/8 in rope).
// BM=128 (8 warps x 16 rows), BN=64, HD=64. V arrives transposed [d][s].
// Smem (halves, pad 72): Ks[2][64][72], Vs[2][64][72], QP[128][72].
// ===========================================================================
#define FPADH 72
#define H_KS0 0
#define H_VS0 (2 * 64 * FPADH)              // 9216
#define H_QP  (4 * 64 * FPADH)              // 18432
#define FLASH_SMEM ((4 * 64 * FPADH + 128 * FPADH) * 2)   // 55296 bytes

__device__ __forceinline__ void flash_load_kv(
    const __half* __restrict__ Kg, const __half* __restrict__ Vtg,
    int tid, uint32_t ks_addr, uint32_t vs_addr)
{
    // K: 64 rows (s) x 64 halves; V: 64 rows (d) x 64 halves (s-slice)
#pragma unroll
    for (int t = 0; t < 2; ++t) {
        int idx = tid + t * 256;    // 0..511
        int row = idx >> 3;
        int c = idx & 7;
        const __half* srcK = Kg + row * HD + c * 8;
        const __half* srcV = Vtg + (size_t)row * SS + c * 8;
        uint32_t dK = ks_addr + (row * FPADH + c * 8) * 2;
        uint32_t dV = vs_addr + (row * FPADH + c * 8) * 2;
        asm volatile("cp.async.cg.shared.global [%0], [%1], 16;" :: "r"(dK), "l"(srcK));
        asm volatile("cp.async.cg.shared.global [%0], [%1], 16;" :: "r"(dV), "l"(srcV));
    }
}

__global__ __launch_bounds__(256, 2)
void flash_h_kernel(const __half* __restrict__ Q, const __half* __restrict__ K,
                    const __half* __restrict__ Vt, __half* __restrict__ O)
{
    extern __shared__ __align__(16) __half sm[];
    const uint32_t sb = smem_u32(sm);

    const int tid = threadIdx.x;
    const int w = tid >> 5;
    const int lane = tid & 31;
    const int lr = lane >> 2;
    const int lc = lane & 3;

    const int qt = (SS / 128 - 1) - blockIdx.x;   // big tiles first
    const int h  = blockIdx.y;
    const int b  = blockIdx.z;
    const int bh = b * HH + h;

    const __half* Qg = Q + ((size_t)bh * SS + qt * 128) * HD;
    const __half* Kb = K + (size_t)bh * SS * HD;
    const __half* Vb = Vt + (size_t)bh * HD * SS;

    // ---- stage Q (128 x 64 halves) into QP ----
    __half* QP = sm + H_QP;
#pragma unroll
    for (int t = 0; t < 4; ++t) {
        int idx = tid + t * 256;    // 0..1023
        int row = idx >> 3;
        int c8 = (idx & 7) * 8;
        *(uint4*)&QP[row * FPADH + c8] = *(const uint4*)(Qg + row * HD + c8);
    }
    __syncthreads();

    // Q fragments (Q already scaled by 1/8)
    uint32_t qa[4][4];
    {
        int r = w * 16 + lr;
#pragma unroll
        for (int kk = 0; kk < 4; ++kk) {
            int k0 = kk * 16 + 2 * lc;
            qa[kk][0] = *(const uint32_t*)&QP[r * FPADH + k0];
            qa[kk][1] = *(const uint32_t*)&QP[(r + 8) * FPADH + k0];
            qa[kk][2] = *(const uint32_t*)&QP[r * FPADH + k0 + 8];
            qa[kk][3] = *(const uint32_t*)&QP[(r + 8) * FPADH + k0 + 8];
        }
    }

    float oacc[8][4];
#pragma unroll
    for (int nt = 0; nt < 8; ++nt)
#pragma unroll
        for (int i = 0; i < 4; ++i) oacc[nt][i] = 0.0f;
    float mA = -INFINITY, mB = -INFINITY, lA = 0.0f, lB = 0.0f;

    const int jmax = 2 * qt + 1;

    flash_load_kv(Kb, Vb, tid, sb + H_KS0 * 2, sb + H_VS0 * 2);
    asm volatile("cp.async.commit_group;" ::: "memory");

    __half* Pt = QP;

    for (int j = 0; j <= jmax; ++j) {
        __syncthreads();

        if (j + 1 <= jmax) {
            int st = (j + 1) & 1;
            flash_load_kv(Kb + (size_t)(j + 1) * 64 * HD,
                          Vb + (size_t)(j + 1) * 64, tid,
                          sb + (H_KS0 + st * 64 * FPADH) * 2,
                          sb + (H_VS0 + st * 64 * FPADH) * 2);
        }
        asm volatile("cp.async.commit_group;" ::: "memory");
        asm volatile("cp.async.wait_group 1;" ::: "memory");
        __syncthreads();

        const int st = j & 1;
        const __half* Ks = sm + H_KS0 + st * 64 * FPADH;
        const __half* Vs = sm + H_VS0 + st * 64 * FPADH;

        // ---- S = (Q/8) K^T ----
        float sacc[8][4];
#pragma unroll
        for (int nt = 0; nt < 8; ++nt)
#pragma unroll
            for (int i = 0; i < 4; ++i) sacc[nt][i] = 0.0f;

#pragma unroll
        for (int kk = 0; kk < 4; ++kk) {
            int k0 = kk * 16 + 2 * lc;
#pragma unroll
            for (int nt = 0; nt < 8; ++nt) {
                int c = nt * 8 + lr;
                uint32_t bf[2];
                bf[0] = *(const uint32_t*)&Ks[c * FPADH + k0];
                bf[1] = *(const uint32_t*)&Ks[c * FPADH + k0 + 8];
                mma_f16(sacc[nt], qa[kk], bf);
            }
        }

        // ---- causal mask ----
        if (j >= 2 * qt) {
            int rowA = qt * 128 + w * 16 + lr;
            int rowB = rowA + 8;
#pragma unroll
            for (int nt = 0; nt < 8; ++nt) {
                int c0 = j * 64 + nt * 8 + 2 * lc;
                int c1 = c0 + 1;
                if (c0 > rowA) sacc[nt][0] = -1.0e30f;
                if (c1 > rowA) sacc[nt][1] = -1.0e30f;
                if (c0 > rowB) sacc[nt][2] = -1.0e30f;
                if (c1 > rowB) sacc[nt][3] = -1.0e30f;
            }
        }

        // ---- online softmax ----
        float mxA = -INFINITY, mxB = -INFINITY;
#pragma unroll
        for (int nt = 0; nt < 8; ++nt) {
            mxA = fmaxf(mxA, fmaxf(sacc[nt][0], sacc[nt][1]));
            mxB = fmaxf(mxB, fmaxf(sacc[nt][2], sacc[nt][3]));
        }
        mxA = fmaxf(mxA, __shfl_xor_sync(0xffffffffu, mxA, 1));
        mxA = fmaxf(mxA, __shfl_xor_sync(0xffffffffu, mxA, 2));
        mxB = fmaxf(mxB, __shfl_xor_sync(0xffffffffu, mxB, 1));
        mxB = fmaxf(mxB, __shfl_xor_sync(0xffffffffu, mxB, 2));

        float mnA = fmaxf(mA, mxA);
        float mnB = fmaxf(mB, mxB);
        float corrA = __expf(mA - mnA);
        float corrB = __expf(mB - mnB);
        mA = mnA; mB = mnB;

        float rsA = 0.0f, rsB = 0.0f;
#pragma unroll
        for (int nt = 0; nt < 8; ++nt) {
            sacc[nt][0] = __expf(sacc[nt][0] - mnA);
            sacc[nt][1] = __expf(sacc[nt][1] - mnA);
            sacc[nt][2] = __expf(sacc[nt][2] - mnB);
            sacc[nt][3] = __expf(sacc[nt][3] - mnB);
            rsA += sacc[nt][0] + sacc[nt][1];
            rsB += sacc[nt][2] + sacc[nt][3];
        }
        rsA += __shfl_xor_sync(0xffffffffu, rsA, 1);
        rsA += __shfl_xor_sync(0xffffffffu, rsA, 2);
        rsB += __shfl_xor_sync(0xffffffffu, rsB, 1);
        rsB += __shfl_xor_sync(0xffffffffu, rsB, 2);
        lA = lA * corrA + rsA;
        lB = lB * corrB + rsB;

#pragma unroll
        for (int nt = 0; nt < 8; ++nt) {
            oacc[nt][0] *= corrA;
            oacc[nt][1] *= corrA;
            oacc[nt][2] *= corrB;
            oacc[nt][3] *= corrB;
        }

        // ---- stage P (half2) into warp-private smem rows ----
        {
            int rA = w * 16 + lr;
#pragma unroll
            for (int nt = 0; nt < 8; ++nt) {
                int c = nt * 8 + 2 * lc;
                *(__half2*)&Pt[rA * FPADH + c] =
                    __floats2half2_rn(sacc[nt][0], sacc[nt][1]);
                *(__half2*)&Pt[(rA + 8) * FPADH + c] =
                    __floats2half2_rn(sacc[nt][2], sacc[nt][3]);
            }
        }
        __syncwarp();

        // ---- O += P V  (V transposed in smem: Vs[d][j]) ----
#pragma unroll
        for (int kk = 0; kk < 4; ++kk) {
            int k0 = kk * 16 + 2 * lc;
            int r = w * 16 + lr;
            uint32_t pa[4];
            pa[0] = *(const uint32_t*)&Pt[r * FPADH + k0];
            pa[1] = *(const uint32_t*)&Pt[(r + 8) * FPADH + k0];
            pa[2] = *(const uint32_t*)&Pt[r * FPADH + k0 + 8];
            pa[3] = *(const uint32_t*)&Pt[(r + 8) * FPADH + k0 + 8];
#pragma unroll
            for (int nt = 0; nt < 8; ++nt) {
                int d = nt * 8 + lr;
                uint32_t bf[2];
                bf[0] = *(const uint32_t*)&Vs[d * FPADH + k0];
                bf[1] = *(const uint32_t*)&Vs[d * FPADH + k0 + 8];
                mma_f16(oacc[nt], pa, bf);
            }
        }
        __syncwarp();
    }

    // ---- epilogue: ctx half [b][row][h*64+d] = o / l ----
    float invA = 1.0f / lA;
    float invB = 1.0f / lB;
    int rowA = qt * 128 + w * 16 + lr;
    __half* Og = O + ((size_t)b * SS) * DD + h * HD;
#pragma unroll
    for (int nt = 0; nt < 8; ++nt) {
        int d = nt * 8 + 2 * lc;
        *(__half2*)&Og[(size_t)rowA * DD + d] =
            __floats2half2_rn(oacc[nt][0] * invA, oacc[nt][1] * invA);
        *(__half2*)&Og[(size_t)(rowA + 8) * DD + d] =
            __floats2half2_rn(oacc[nt][2] * invB, oacc[nt][3] * invB);
    }
}

// ---------------------------------------------------------------------------
// kernel_launch
// Input order: x, mask, rope_cos, rope_sin, Wq, bq, Wk, bk, Wv, bv, Wo, bo
// ---------------------------------------------------------------------------
extern "C" void kernel_launch(void* const* d_in, const int* in_sizes, int n_in,
                              void* d_out, int out_size)
{
    (void)in_sizes; (void)n_in; (void)out_size;

    const float* x    = (const float*)d_in[0];
    const float* cosb = (const float*)d_in[2];
    const float* sinb = (const float*)d_in[3];
    const float* Wq = (const float*)d_in[4];
    const float* bq = (const float*)d_in[5];
    const float* Wk = (const float*)d_in[6];
    const float* bk = (const float*)d_in[7];
    const float* Wv = (const float*)d_in[8];
    const float* bv = (const float*)d_in[9];
    const float* Wo = (const float*)d_in[10];
    const float* bo = (const float*)d_in[11];
    float* out = (float*)d_out;

    __half *Qh, *Kh, *Vt, *Ch, *Xh, *Wh;
    cudaGetSymbolAddress((void**)&Qh, g_Qh);
    cudaGetSymbolAddress((void**)&Kh, g_Kh);
    cudaGetSymbolAddress((void**)&Vt, g_Vt);
    cudaGetSymbolAddress((void**)&Ch, g_ctx);
    cudaGetSymbolAddress((void**)&Xh, g_Xh);
    cudaGetSymbolAddress((void**)&Wh, g_Wh);

    cudaFuncSetAttribute(gemm_h_kernel<0>,
                         cudaFuncAttributeMaxDynamicSharedMemorySize, GEMM_SMEM);
    cudaFuncSetAttribute(gemm_h_kernel<1>,
                         cudaFuncAttributeMaxDynamicSharedMemorySize, GEMM_SMEM);
    cudaFuncSetAttribute(gemm_h_kernel<2>,
                         cudaFuncAttributeMaxDynamicSharedMemorySize, GEMM_SMEM);
    cudaFuncSetAttribute(flash_h_kernel,
                         cudaFuncAttributeMaxDynamicSharedMemorySize, FLASH_SMEM);

    // --- convert inputs to fp16 ---
    cvt_kernel<<<(MROWS * DD / 4 + 255) / 256, 256>>>(x, Xh, MROWS * DD / 4);
    cvt_kernel<<<(DD * DD / 4 + 255) / 256, 256>>>(Wq, Wh + 0 * DD * DD, DD * DD / 4);
    cvt_kernel<<<(DD * DD / 4 + 255) / 256, 256>>>(Wk, Wh + 1 * DD * DD, DD * DD / 4);
    cvt_kernel<<<(DD * DD / 4 + 255) / 256, 256>>>(Wv, Wh + 2 * DD * DD, DD * DD / 4);
    cvt_kernel<<<(DD * DD / 4 + 255) / 256, 256>>>(Wo, Wh + 3 * DD * DD, DD * DD / 4);

    dim3 ggrid(DD / 128, MROWS / 128);   // (8, 64) = 512 CTAs

    gemm_h_kernel<0><<<ggrid, 256, GEMM_SMEM>>>(Xh, Wh + 0 * DD * DD, bq, Qh);
    gemm_h_kernel<0><<<ggrid, 256, GEMM_SMEM>>>(Xh, Wh + 1 * DD * DD, bk, Kh);
    gemm_h_kernel<1><<<ggrid, 256, GEMM_SMEM>>>(Xh, Wh + 2 * DD * DD, bv, Vt);

    int rope_threads = BB * HH * SS * 32;
    rope_h_kernel<true><<<rope_threads / 256, 256>>>(Qh, cosb, sinb);
    rope_h_kernel<false><<<rope_threads / 256, 256>>>(Kh, cosb, sinb);

    flash_h_kernel<<<dim3(SS / 128, HH, BB), 256, FLASH_SMEM>>>(Qh, Kh, Vt, Ch);

    gemm_h_kernel<2><<<ggrid, 256, GEMM_SMEM>>>(Ch, Wh + 3 * DD * DD, bo, out);
}